// round 11
// baseline (speedup 1.0000x reference)
#include <cuda_runtime.h>
#include <cuda_bf16.h>
#include <cstdint>

#define Bsz 64
#define Tsz 512
#define Isz 512
#define Hsz 512

// ---------------------------------------------------------------------------
// Static device scratch
// ---------------------------------------------------------------------------
// 16 independent chain counters (8 btile x 2 dir), padded to 128B each
struct GCnt { unsigned v; unsigned pad[31]; };
__device__ GCnt g_gcount[16];

__global__ void reset_bar_kernel() {
    if (threadIdx.x < 16) g_gcount[threadIdx.x].v = 0;
}

// ---------------------------------------------------------------------------
// Packed fp32x2 helpers (Blackwell FFMA2 path)
// ---------------------------------------------------------------------------
typedef unsigned long long ull;

__device__ __forceinline__ ull ffma2(ull a, ull b, ull c) {
    ull d;
    asm("fma.rn.f32x2 %0, %1, %2, %3;" : "=l"(d) : "l"(a), "l"(b), "l"(c));
    return d;
}
__device__ __forceinline__ ull pack2(float x) {
    ull d;
    asm("mov.b64 %0, {%1, %1};" : "=l"(d) : "f"(x));
    return d;
}
__device__ __forceinline__ ull pack2f(float x, float y) {
    ull d;
    asm("mov.b64 %0, {%1, %2};" : "=l"(d) : "f"(x), "f"(y));
    return d;
}
__device__ __forceinline__ float2 unpack2(ull a) {
    float2 r;
    asm("mov.b64 {%0, %1}, %2;" : "=f"(r.x), "=f"(r.y) : "l"(a));
    return r;
}

// ---------------------------------------------------------------------------
// Fused persistent kernel: scan (warps 0-7) + xproj producer (warps 8-15).
// 128 CTAs = 8 btile x 16 ctile; CTA owns 8 batches x 32 cols x 2 dirs.
//   warps 0-3 : fwd scan      warps 4-7  : bwd scan
//   warps 8-11: fwd xp prod   warps 12-15: bwd xp prod
// Per step s: scan consumes xp[dir][s&1] (smem), h from L2 (y), writes y,
// arrives on its (btile,dir) chain counter. Producer computes xp for s+1
// (x @ Wx^T + b, W streamed from L2) into xp[dir][(s+1)&1], then both halves
// of that dir meet at a 256-thread named barrier.
//
// smem (floats):
//   WS[dir][kc][q*4+j][c]  (Wh, chunk stride 516 = odd 16B units)
//   xp [dir][buf][8b * 32c]
// ---------------------------------------------------------------------------
#define SCAN_CTAS 128
#define WSZ (32 * 516)
#define XPOFF (2 * WSZ)

__global__ void __launch_bounds__(512, 1) scan_fused_kernel(
    const float* __restrict__ x,
    const float* __restrict__ h0f, const float* __restrict__ h0b,
    const float* __restrict__ Whf, const float* __restrict__ Whb,
    const float* __restrict__ Wxf, const float* __restrict__ bxf,
    const float* __restrict__ Wxb, const float* __restrict__ bxb,
    float* __restrict__ y)
{
    extern __shared__ float sm[];

    const int cta   = blockIdx.x;
    const int btile = cta >> 4;
    const int ctile = cta & 15;
    const int b0    = btile << 3;   // 8 batches
    const int cbase = ctile << 5;   // 32 cols

    const int tid  = threadIdx.x;
    const int warp = tid >> 5;
    const int lane = tid & 31;
    const int role = warp >> 3;       // 0 scan, 1 producer
    const int dir  = (warp >> 2) & 1;
    const int hw   = warp & 3;        // warp within quad
    const int c0   = hw << 3;         // 8 local cols
    const int gidx = (btile << 1) | dir;

    float* WS  = sm + dir * WSZ;
    float* xps = sm + XPOFF;          // [dir][buf][256]

    // ---- load Wh slices for both dirs (all 512 threads) ----
    // WS[d][kc][q*4+j][c] = Wh_d[cbase+c][q*128 + kc*4 + j]
    for (int i = tid; i < 2 * 32 * 128; i += 512) {
        int d  = i >> 12;
        int j2 = i & 4095;
        int c  = j2 >> 7;
        int k4 = (j2 & 127) * 4;
        const float* Whd = d ? Whb : Whf;
        float4 v = *(const float4*)(Whd + (size_t)(cbase + c) * Hsz + k4);
        int q  = k4 >> 7;
        int kcx = (k4 & 127) >> 2;
        float* p = sm + d * WSZ + kcx * 516 + (q * 4) * 32 + c;
        p[0 * 32] = v.x; p[1 * 32] = v.y; p[2 * 32] = v.z; p[3 * 32] = v.w;
    }
    __syncthreads();

    const int kc = lane;
    // lane's 2 outputs after the halving butterfly (o = b_local*8 + c_local)
    const int o0 = ((lane & 1) << 5) | (((lane >> 1) & 1) << 4) |
                   (((lane >> 2) & 1) << 3) | (((lane >> 3) & 1) << 2) |
                   (((lane >> 4) & 1) << 1);
    const int bl    = o0 >> 3;
    const int b_out = b0 + bl;
    const int colg  = cbase + c0 + (o0 & 7);
    const int xslot = bl * 32 + c0 + (o0 & 7);   // within xp[dir][buf]

    const int barS = 1 + dir;   // scan-internal, 128 threads
    const int barH = 3 + dir;   // handoff, 256 threads

    if (role == 1) {
        // =================== xproj producer half ===================
        const float* __restrict__ Wx = dir ? Wxb : Wxf;
        const float* __restrict__ bx = dir ? bxb : bxf;
        const float2 bias = make_float2(__ldg(bx + colg), __ldg(bx + colg + 1));
        const size_t xbstride = (size_t)Tsz * Isz;

        for (int s = -1; s < Tsz; s++) {
            const int sp = s + 1;
            if (sp < Tsz) {
                const int t = dir ? (Tsz - 1 - sp) : sp;
                const float* xb = x + ((size_t)b0 * Tsz + t) * Isz + (kc << 2);
                const float* wb = Wx + (size_t)(cbase + c0) * Isz + (kc << 2);

                ull acc[8][4];   // [c][b-pair]
#pragma unroll
                for (int c = 0; c < 8; c++)
#pragma unroll
                    for (int p = 0; p < 4; p++) acc[c][p] = 0ull;

                float4 xq[8], wq[8], xn[8], wn[8];
#pragma unroll
                for (int b = 0; b < 8; b++)
                    xq[b] = __ldcg((const float4*)(xb + b * xbstride));
#pragma unroll
                for (int c = 0; c < 8; c++)
                    wq[c] = *(const float4*)(wb + c * Isz);

#pragma unroll
                for (int q = 0; q < 4; q++) {
                    if (q < 3) {
#pragma unroll
                        for (int b = 0; b < 8; b++)
                            xn[b] = __ldcg((const float4*)(xb + (q + 1) * 128 + b * xbstride));
#pragma unroll
                        for (int c = 0; c < 8; c++)
                            wn[c] = *(const float4*)(wb + (q + 1) * 128 + c * Isz);
                    }
#pragma unroll
                    for (int j = 0; j < 4; j++) {
                        ull xp2[4];
#pragma unroll
                        for (int p = 0; p < 4; p++) {
                            float xa = (j == 0) ? xq[2 * p].x : (j == 1) ? xq[2 * p].y
                                     : (j == 2) ? xq[2 * p].z : xq[2 * p].w;
                            float xbv = (j == 0) ? xq[2 * p + 1].x : (j == 1) ? xq[2 * p + 1].y
                                      : (j == 2) ? xq[2 * p + 1].z : xq[2 * p + 1].w;
                            xp2[p] = pack2f(xa, xbv);
                        }
#pragma unroll
                        for (int c = 0; c < 8; c++) {
                            float wsc = (j == 0) ? wq[c].x : (j == 1) ? wq[c].y
                                      : (j == 2) ? wq[c].z : wq[c].w;
                            ull wp2 = pack2(wsc);
#pragma unroll
                            for (int p = 0; p < 4; p++)
                                acc[c][p] = ffma2(wp2, xp2[p], acc[c][p]);
                        }
                    }
                    if (q < 3) {
#pragma unroll
                        for (int b = 0; b < 8; b++) xq[b] = xn[b];
#pragma unroll
                        for (int c = 0; c < 8; c++) wq[c] = wn[c];
                    }
                }

                // unpack: acc[c][p] -> v[(2p)*8+c], v[(2p+1)*8+c]
                float v[64];
#pragma unroll
                for (int c = 0; c < 8; c++)
#pragma unroll
                    for (int p = 0; p < 4; p++) {
                        float2 u = unpack2(acc[c][p]);
                        v[(2 * p) * 8 + c]     = u.x;
                        v[(2 * p + 1) * 8 + c] = u.y;
                    }

                // 5-level jammed halving butterfly
                int n = 64;
#pragma unroll
                for (int m = 1; m < 32; m <<= 1) {
                    n >>= 1;
                    const bool hi = (lane & m) != 0;
#pragma unroll
                    for (int i = 0; i < n; i++) {
                        float send = hi ? v[i] : v[i + n];
                        float keep = hi ? v[i + n] : v[i];
                        v[i] = keep + __shfl_xor_sync(0xffffffffu, send, m);
                    }
                }

                float2 o = make_float2(v[0] + bias.x, v[1] + bias.y);
                *(float2*)&xps[(dir * 2 + (sp & 1)) * 256 + xslot] = o;
            }
            asm volatile("bar.sync %0, 256;" :: "r"(barH) : "memory");
        }
    } else {
        // =================== scan half ===================
        const float* __restrict__ h0 = dir ? h0b : h0f;
        const int htid = tid & 127;
        volatile unsigned* vcnt = &g_gcount[gidx].v;

        const float* wp = WS + kc * 516 + c0;

        asm volatile("bar.sync %0, 256;" :: "r"(barH) : "memory");  // xp[0] ready

        for (int step = 0; step < Tsz; step++) {
            const int t = dir ? (Tsz - 1 - step) : step;

            // ---- wait for the 16 group CTAs to finish step-1 ----
            if (htid == 0 && step > 0) {
                unsigned tgt = (unsigned)(16 * step);
                while (*vcnt < tgt) { }
                __threadfence();
            }
            asm volatile("bar.sync %0, 128;" :: "r"(barS) : "memory");

            // ---- h source (lane reads own k-subset via L2) ----
            const float* hsrc;
            size_t rstride;
            if (step == 0) {
                hsrc = h0 + (size_t)b0 * Hsz; rstride = Hsz;
            } else {
                int tp = dir ? (t + 1) : (t - 1);
                hsrc = y + ((size_t)b0 * Tsz + tp) * (2 * Hsz) + ((size_t)dir << 9);
                rstride = (size_t)Tsz * 2 * Hsz;
            }
            const float* hbase = hsrc + (kc << 2);

            ull acc[8][4];
#pragma unroll
            for (int b = 0; b < 8; b++)
#pragma unroll
                for (int j = 0; j < 4; j++) acc[b][j] = 0ull;

            float4 hq[8], hn[8];
#pragma unroll
            for (int b = 0; b < 8; b++)
                hq[b] = __ldcg((const float4*)(hbase + b * rstride));

#pragma unroll
            for (int q = 0; q < 4; q++) {
                if (q < 3) {
#pragma unroll
                    for (int b = 0; b < 8; b++)
                        hn[b] = __ldcg((const float4*)(hbase + (q + 1) * 128 + b * rstride));
                }
#pragma unroll
                for (int j = 0; j < 4; j++) {
                    const float* wrow = wp + (q * 4 + j) * 32;
                    ulonglong2 wa = *(const ulonglong2*)(wrow);
                    ulonglong2 wb = *(const ulonglong2*)(wrow + 4);
#pragma unroll
                    for (int b = 0; b < 8; b++) {
                        float hs = (j == 0) ? hq[b].x : (j == 1) ? hq[b].y
                                 : (j == 2) ? hq[b].z : hq[b].w;
                        ull hpk = pack2(hs);
                        acc[b][0] = ffma2(hpk, wa.x, acc[b][0]);
                        acc[b][1] = ffma2(hpk, wa.y, acc[b][1]);
                        acc[b][2] = ffma2(hpk, wb.x, acc[b][2]);
                        acc[b][3] = ffma2(hpk, wb.y, acc[b][3]);
                    }
                }
                if (q < 3) {
#pragma unroll
                    for (int b = 0; b < 8; b++) hq[b] = hn[b];
                }
            }

            float v[64];
#pragma unroll
            for (int b = 0; b < 8; b++)
#pragma unroll
                for (int cp = 0; cp < 4; cp++) {
                    float2 u = unpack2(acc[b][cp]);
                    v[b * 8 + cp * 2]     = u.x;
                    v[b * 8 + cp * 2 + 1] = u.y;
                }

            int n = 64;
#pragma unroll
            for (int m = 1; m < 32; m <<= 1) {
                n >>= 1;
                const bool hi = (lane & m) != 0;
#pragma unroll
                for (int i = 0; i < n; i++) {
                    float send = hi ? v[i] : v[i + n];
                    float keep = hi ? v[i + n] : v[i];
                    v[i] = keep + __shfl_xor_sync(0xffffffffu, send, m);
                }
            }

            // xp from smem (produced one step ahead by the producer half)
            const float2 xpv = *(const float2*)&xps[(dir * 2 + (step & 1)) * 256 + xslot];

            float r0 = tanhf(v[0] + xpv.x);
            float r1 = tanhf(v[1] + xpv.y);

            float* yp = y + ((size_t)b_out * Tsz + t) * (2 * Hsz) + (dir << 9) + colg;
            __stcg((float2*)yp, make_float2(r0, r1));

            // ---- order stores, arrive on chain counter ----
            asm volatile("bar.sync %0, 128;" :: "r"(barS) : "memory");
            if (htid == 0) {
                __threadfence();
                atomicAdd((unsigned*)&g_gcount[gidx].v, 1u);
            }
            asm volatile("bar.sync %0, 256;" :: "r"(barH) : "memory");
        }
    }
}

// ---------------------------------------------------------------------------
// Tail: hT_f = hs_f[T-1], hT_b = hs_b[t=0]
// ---------------------------------------------------------------------------
__global__ void tail_kernel(float* __restrict__ out)
{
    const int b = blockIdx.x;
    const int k = threadIdx.x;
    const float* y = out;
    const size_t yN = (size_t)Bsz * Tsz * 2 * Hsz;
    out[yN + (size_t)b * Hsz + k] =
        y[((size_t)b * Tsz + (Tsz - 1)) * (2 * Hsz) + k];
    out[yN + (size_t)Bsz * Hsz + (size_t)b * Hsz + k] =
        y[((size_t)b * Tsz) * (2 * Hsz) + Hsz + k];
}

// ---------------------------------------------------------------------------
extern "C" void kernel_launch(void* const* d_in, const int* in_sizes, int n_in,
                              void* d_out, int out_size)
{
    const float* x     = (const float*)d_in[0];
    const float* h0f   = (const float*)d_in[1];
    const float* h0b   = (const float*)d_in[2];
    const float* Wxf_w = (const float*)d_in[3];
    const float* Wxf_b = (const float*)d_in[4];
    const float* Whf_w = (const float*)d_in[5];
    const float* Wxb_w = (const float*)d_in[6];
    const float* Wxb_b = (const float*)d_in[7];
    const float* Whb_w = (const float*)d_in[8];
    float* out = (float*)d_out;

    const int scan_smem = (2 * WSZ + 2 * 2 * 256) * (int)sizeof(float);  // 136192 B
    cudaFuncSetAttribute(scan_fused_kernel,
                         cudaFuncAttributeMaxDynamicSharedMemorySize, scan_smem);

    reset_bar_kernel<<<1, 32>>>();

    scan_fused_kernel<<<SCAN_CTAS, 512, scan_smem>>>(
        x, h0f, h0b, Whf_w, Whb_w, Wxf_w, Wxf_b, Wxb_w, Wxb_b, out);

    tail_kernel<<<Bsz, Hsz>>>(out);
}

// round 12
// speedup vs baseline: 1.4226x; 1.4226x over previous
#include <cuda_runtime.h>
#include <cuda_bf16.h>
#include <cstdint>

#define Bsz 64
#define Tsz 512
#define Isz 512
#define Hsz 512

// ---------------------------------------------------------------------------
// Static device scratch
// ---------------------------------------------------------------------------
__device__ float g_xproj[2u * Tsz * Bsz * Hsz];   // [d][t][b][h]

// 16 independent chain counters (8 btile x 2 dir), padded to 128B each
struct GCnt { unsigned v; unsigned pad[31]; };
__device__ GCnt g_gcount[16];

__global__ void reset_bar_kernel() {
    if (threadIdx.x < 16) g_gcount[threadIdx.x].v = 0;
}

// ---------------------------------------------------------------------------
// Packed fp32x2 helpers (Blackwell FFMA2 path)
// ---------------------------------------------------------------------------
typedef unsigned long long ull;

__device__ __forceinline__ ull ffma2(ull a, ull b, ull c) {
    ull d;
    asm("fma.rn.f32x2 %0, %1, %2, %3;" : "=l"(d) : "l"(a), "l"(b), "l"(c));
    return d;
}
__device__ __forceinline__ ull pack2(float x) {
    ull d;
    asm("mov.b64 %0, {%1, %1};" : "=l"(d) : "f"(x));
    return d;
}
__device__ __forceinline__ float2 unpack2(ull a) {
    float2 r;
    asm("mov.b64 {%0, %1}, %2;" : "=f"(r.x), "=f"(r.y) : "l"(a));
    return r;
}

// ---------------------------------------------------------------------------
// Scoped sync primitives (release-publish / acquire-consume, no sc fences)
// ---------------------------------------------------------------------------
__device__ __forceinline__ unsigned ld_acq_gpu(const unsigned* p) {
    unsigned v;
    asm volatile("ld.acquire.gpu.global.u32 %0, [%1];" : "=r"(v) : "l"(p) : "memory");
    return v;
}
__device__ __forceinline__ void red_rel_gpu(unsigned* p) {
    asm volatile("red.release.gpu.global.add.u32 [%0], 1;" :: "l"(p) : "memory");
}

// ---------------------------------------------------------------------------
// Phase 1: xproj = x @ Wx^T + b.  (unchanged — measured 641us, fma=67%)
// ---------------------------------------------------------------------------
__global__ void __launch_bounds__(256, 2) xproj_gemm_kernel(
    const float* __restrict__ x,
    const float* __restrict__ Wf, const float* __restrict__ bf,
    const float* __restrict__ Wb, const float* __restrict__ bb)
{
    const int d = blockIdx.z;
    const float* __restrict__ W    = d ? Wb : Wf;
    const float* __restrict__ bias = d ? bb : bf;

    const int mt = blockIdx.y << 7;
    const int b  = mt >> 9;
    const int t0 = mt & 511;
    const int n0 = blockIdx.x << 7;

    __shared__ float sA[8][132];
    __shared__ float sB[8][132];

    const int tid = threadIdx.x;
    const int r  = tid >> 1;
    const int cc = (tid & 1) * 4;

    const float* ap = x + ((size_t)(b * Tsz + t0 + r)) * Isz + cc;
    const float* bp = W + ((size_t)(n0 + r)) * Isz + cc;

    float4 ra = *(const float4*)ap;
    float4 rb = *(const float4*)bp;

    const int tr = tid >> 4;
    const int tc = tid & 15;

    ull acc2[8][4];
#pragma unroll
    for (int i = 0; i < 8; i++)
#pragma unroll
        for (int j = 0; j < 4; j++) acc2[i][j] = 0ull;

    for (int k0 = 0; k0 < Isz; k0 += 8) {
        __syncthreads();
        sA[cc + 0][r] = ra.x; sA[cc + 1][r] = ra.y;
        sA[cc + 2][r] = ra.z; sA[cc + 3][r] = ra.w;
        sB[cc + 0][r] = rb.x; sB[cc + 1][r] = rb.y;
        sB[cc + 2][r] = rb.z; sB[cc + 3][r] = rb.w;
        __syncthreads();

        if (k0 + 8 < Isz) {
            ra = *(const float4*)(ap + k0 + 8);
            rb = *(const float4*)(bp + k0 + 8);
        }

#pragma unroll
        for (int k = 0; k < 8; k++) {
            float4 a0 = *(const float4*)&sA[k][tr * 4];
            float4 a1 = *(const float4*)&sA[k][64 + tr * 4];
            ulonglong2 b0q = *(const ulonglong2*)&sB[k][tc * 4];
            ulonglong2 b1q = *(const ulonglong2*)&sB[k][64 + tc * 4];
            float am[8] = {a0.x, a0.y, a0.z, a0.w, a1.x, a1.y, a1.z, a1.w};
#pragma unroll
            for (int i = 0; i < 8; i++) {
                ull apk = pack2(am[i]);
                acc2[i][0] = ffma2(apk, b0q.x, acc2[i][0]);
                acc2[i][1] = ffma2(apk, b0q.y, acc2[i][1]);
                acc2[i][2] = ffma2(apk, b1q.x, acc2[i][2]);
                acc2[i][3] = ffma2(apk, b1q.y, acc2[i][3]);
            }
        }
    }

    float4 bias0 = *(const float4*)(bias + n0 + tc * 4);
    float4 bias1 = *(const float4*)(bias + n0 + 64 + tc * 4);

#pragma unroll
    for (int mi = 0; mi < 8; mi++) {
        int rloc = (mi < 4) ? (tr * 4 + mi) : (64 + tr * 4 + (mi - 4));
        int t = t0 + rloc;
        float* op = g_xproj + (((size_t)d * Tsz + t) * Bsz + b) * Hsz + n0;
        float2 p0 = unpack2(acc2[mi][0]);
        float2 p1 = unpack2(acc2[mi][1]);
        float2 p2 = unpack2(acc2[mi][2]);
        float2 p3 = unpack2(acc2[mi][3]);
        float4 o0, o1;
        o0.x = p0.x + bias0.x; o0.y = p0.y + bias0.y;
        o0.z = p1.x + bias0.z; o0.w = p1.y + bias0.w;
        o1.x = p2.x + bias1.x; o1.y = p2.y + bias1.y;
        o1.z = p3.x + bias1.z; o1.w = p3.y + bias1.w;
        *(float4*)(op + tc * 4)      = o0;
        *(float4*)(op + 64 + tc * 4) = o1;
    }
}

// ---------------------------------------------------------------------------
// Phase 2: persistent scan, warp-decoupled chain sync.
// 128 CTAs = 8 btile x 16 ctile; CTA owns 8 batches x 32 cols x 2 dirs.
// Warps 0-3 = fwd, warps 4-7 = bwd. Each WARP is an independent agent:
// it polls its (btile,dir) counter (ld.acquire), computes its 8-col slice
// with h read directly from L2 (y), stores, then lane0 red.release-arrives.
// 64 arrivals per group per step (16 CTAs x 4 warps). No bar.sync, no
// sc-fences in the loop.
//
// smem: WS[dir][kc][q*4+j][c], chunk stride 516 floats (odd 16B units).
// ---------------------------------------------------------------------------
#define SCAN_CTAS 128
#define WSZ (32 * 516)

__global__ void __launch_bounds__(256) scan_kernel(
    const float* __restrict__ h0f, const float* __restrict__ h0b,
    const float* __restrict__ Whf, const float* __restrict__ Whb,
    float* __restrict__ y)
{
    extern __shared__ float sm[];

    const int cta   = blockIdx.x;
    const int btile = cta >> 4;
    const int ctile = cta & 15;
    const int b0    = btile << 3;   // 8 batches
    const int cbase = ctile << 5;   // 32 cols

    const int tid  = threadIdx.x;
    const int dir  = tid >> 7;      // 0 fwd (warps 0-3), 1 bwd (warps 4-7)
    const int htid = tid & 127;
    const int hw   = htid >> 5;     // warp within half
    const int lane = tid & 31;
    const int gidx = (btile << 1) | dir;

    const float* __restrict__ Wh = dir ? Whb : Whf;
    const float* __restrict__ h0 = dir ? h0b : h0f;

    float* WS = sm + dir * WSZ;

    // ---- load this dir's W slice once, permuted to the lane K-subsets ----
    // WS[kc][q*4+j][c] = Wh[cbase+c][q*128 + kc*4 + j]
    for (int i = htid; i < 32 * 128; i += 128) {
        int c  = i >> 7;
        int k4 = (i & 127) * 4;
        float4 v = *(const float4*)(Wh + (size_t)(cbase + c) * Hsz + k4);
        int q  = k4 >> 7;
        int kc = (k4 & 127) >> 2;
        float* p = WS + kc * 516 + (q * 4) * 32 + c;
        p[0 * 32] = v.x; p[1 * 32] = v.y; p[2 * 32] = v.z; p[3 * 32] = v.w;
    }
    __syncthreads();

    const int kc = lane;
    const int c0 = hw << 3;         // warp's 8 local cols

    // lane's 2 outputs after the halving butterfly (o = b_local*8 + c_local)
    const int o0 = ((lane & 1) << 5) | (((lane >> 1) & 1) << 4) |
                   (((lane >> 2) & 1) << 3) | (((lane >> 3) & 1) << 2) |
                   (((lane >> 4) & 1) << 1);
    const int b_out = b0 + (o0 >> 3);
    const int colg  = cbase + c0 + (o0 & 7);

    const float* wp = WS + kc * 516 + c0;

    unsigned* cnt = (unsigned*)&g_gcount[gidx].v;

    for (int step = 0; step < Tsz; step++) {
        const int t = dir ? (Tsz - 1 - step) : step;

        // xproj prefetch (chain-independent, in flight during the poll)
        const float2 xp = __ldcg((const float2*)(
            g_xproj + (((size_t)dir * Tsz + t) * Bsz + b_out) * Hsz + colg));

        // ---- warp-local poll: 64 arrivals per completed step ----
        if (step > 0) {
            const unsigned tgt = (unsigned)(step << 6);
            while (ld_acq_gpu(cnt) < tgt) { }
        }

        // ---- h source for this step (lane reads its own k-subset via L2) ----
        const float* hsrc;
        size_t rstride;
        if (step == 0) {
            hsrc = h0 + (size_t)b0 * Hsz; rstride = Hsz;
        } else {
            int tp = dir ? (t + 1) : (t - 1);
            hsrc = y + ((size_t)b0 * Tsz + tp) * (2 * Hsz) + ((size_t)dir << 9);
            rstride = (size_t)Tsz * 2 * Hsz;
        }
        const float* hbase = hsrc + (kc << 2);   // + q*128 + b*rstride

        ull acc[8][4];
#pragma unroll
        for (int b = 0; b < 8; b++)
#pragma unroll
            for (int j = 0; j < 4; j++) acc[b][j] = 0ull;

        // q-double-buffered direct loads
        float4 hq[8], hn[8];
#pragma unroll
        for (int b = 0; b < 8; b++)
            hq[b] = __ldcg((const float4*)(hbase + b * rstride));

#pragma unroll
        for (int q = 0; q < 4; q++) {
            if (q < 3) {
#pragma unroll
                for (int b = 0; b < 8; b++)
                    hn[b] = __ldcg((const float4*)(hbase + (q + 1) * 128 + b * rstride));
            }
#pragma unroll
            for (int j = 0; j < 4; j++) {
                const float* wrow = wp + (q * 4 + j) * 32;
                ulonglong2 wa = *(const ulonglong2*)(wrow);
                ulonglong2 wb = *(const ulonglong2*)(wrow + 4);
#pragma unroll
                for (int b = 0; b < 8; b++) {
                    float hs = (j == 0) ? hq[b].x : (j == 1) ? hq[b].y
                             : (j == 2) ? hq[b].z : hq[b].w;
                    ull hpk = pack2(hs);
                    acc[b][0] = ffma2(hpk, wa.x, acc[b][0]);
                    acc[b][1] = ffma2(hpk, wa.y, acc[b][1]);
                    acc[b][2] = ffma2(hpk, wb.x, acc[b][2]);
                    acc[b][3] = ffma2(hpk, wb.y, acc[b][3]);
                }
            }
            if (q < 3) {
#pragma unroll
                for (int b = 0; b < 8; b++) hq[b] = hn[b];
            }
        }

        // ---- unpack to 64 scalars (o = b*8 + c) ----
        float v[64];
#pragma unroll
        for (int b = 0; b < 8; b++)
#pragma unroll
            for (int cp = 0; cp < 4; cp++) {
                float2 u = unpack2(acc[b][cp]);
                v[b * 8 + cp * 2]     = u.x;
                v[b * 8 + cp * 2 + 1] = u.y;
            }

        // ---- 5-level jammed halving butterfly over the 32 kc lanes ----
        int n = 64;
#pragma unroll
        for (int m = 1; m < 32; m <<= 1) {
            n >>= 1;
            const bool hi = (lane & m) != 0;
#pragma unroll
            for (int i = 0; i < n; i++) {
                float send = hi ? v[i] : v[i + n];
                float keep = hi ? v[i + n] : v[i];
                v[i] = keep + __shfl_xor_sync(0xffffffffu, send, m);
            }
        }

        float r0 = tanhf(v[0] + xp.x);
        float r1 = tanhf(v[1] + xp.y);

        float* yp = y + ((size_t)b_out * Tsz + t) * (2 * Hsz) + (dir << 9) + colg;
        __stcg((float2*)yp, make_float2(r0, r1));

        // ---- warp arrive: syncwarp orders lane stores, lane0 publishes ----
        __syncwarp();
        if (lane == 0) red_rel_gpu(cnt);
    }
}

// ---------------------------------------------------------------------------
// Tail: hT_f = hs_f[T-1], hT_b = hs_b[t=0]
// ---------------------------------------------------------------------------
__global__ void tail_kernel(float* __restrict__ out)
{
    const int b = blockIdx.x;
    const int k = threadIdx.x;
    const float* y = out;
    const size_t yN = (size_t)Bsz * Tsz * 2 * Hsz;
    out[yN + (size_t)b * Hsz + k] =
        y[((size_t)b * Tsz + (Tsz - 1)) * (2 * Hsz) + k];
    out[yN + (size_t)Bsz * Hsz + (size_t)b * Hsz + k] =
        y[((size_t)b * Tsz) * (2 * Hsz) + Hsz + k];
}

// ---------------------------------------------------------------------------
extern "C" void kernel_launch(void* const* d_in, const int* in_sizes, int n_in,
                              void* d_out, int out_size)
{
    const float* x     = (const float*)d_in[0];
    const float* h0f   = (const float*)d_in[1];
    const float* h0b   = (const float*)d_in[2];
    const float* Wxf_w = (const float*)d_in[3];
    const float* Wxf_b = (const float*)d_in[4];
    const float* Whf_w = (const float*)d_in[5];
    const float* Wxb_w = (const float*)d_in[6];
    const float* Wxb_b = (const float*)d_in[7];
    const float* Whb_w = (const float*)d_in[8];
    float* out = (float*)d_out;

    const int scan_smem = (2 * WSZ) * (int)sizeof(float);  // 132096 B
    cudaFuncSetAttribute(scan_kernel,
                         cudaFuncAttributeMaxDynamicSharedMemorySize, scan_smem);

    reset_bar_kernel<<<1, 32>>>();

    dim3 ggrid(4, 256, 2);
    xproj_gemm_kernel<<<ggrid, 256>>>(x, Wxf_w, Wxf_b, Wxb_w, Wxb_b);

    scan_kernel<<<SCAN_CTAS, 256, scan_smem>>>(h0f, h0b, Whf_w, Whb_w, out);

    tail_kernel<<<Bsz, Hsz>>>(out);
}